// round 4
// baseline (speedup 1.0000x reference)
#include <cuda_runtime.h>

#define SEQ   1024
#define BATCH 2048
#define HID   64
#define G4    256     // 4*HID
#define XCHUNK 256

typedef unsigned long long u64;

__device__ __forceinline__ u64 fma2(u64 a, u64 b, u64 c) {
    u64 d;
    asm("fma.rn.f32x2 %0, %1, %2, %3;" : "=l"(d) : "l"(a), "l"(b), "l"(c));
    return d;
}
__device__ __forceinline__ u64 add2(u64 a, u64 b) {
    u64 d;
    asm("add.rn.f32x2 %0, %1, %2;" : "=l"(d) : "l"(a), "l"(b));
    return d;
}
__device__ __forceinline__ u64 pack2(float a, float b) {
    u64 r;
    asm("mov.b64 %0, {%1, %2};" : "=l"(r) : "f"(a), "f"(b));
    return r;
}
__device__ __forceinline__ float2 unpack2(u64 v) {
    float2 f;
    asm("mov.b64 {%0, %1}, %2;" : "=f"(f.x), "=f"(f.y) : "l"(v));
    return f;
}

__device__ __forceinline__ float fast_sigmoid(float v) {
    return __fdividef(1.0f, 1.0f + __expf(-v));
}
__device__ __forceinline__ float fast_tanh(float v) {
    return 2.0f * __fdividef(1.0f, 1.0f + __expf(-2.0f * v)) - 1.0f;
}

__global__ void __launch_bounds__(256, 2)
lstm_fused_kernel(const float* __restrict__ x,
                  const float* __restrict__ W_ih,
                  const float* __restrict__ W_hh,
                  const float* __restrict__ b_ih,
                  const float* __restrict__ b_hh,
                  const float* __restrict__ fc1_w,
                  const float* __restrict__ fc1_b,
                  const float* __restrict__ fc2_w,
                  const float* __restrict__ fc2_b,
                  float* __restrict__ out)
{
    const int b = blockIdx.x;      // batch element
    const int j = threadIdx.x;     // gate row 0..255 (i:0-63, f:64-127, g:128-191, o:192-255)

    __shared__ u64   sh_h[HID / 2];   // h as 32 packed f32x2
    __shared__ float sh_g[G4];        // activated gates
    __shared__ float sh_x[XCHUNK];    // staged x column
    __shared__ float sh_c[HID];       // cell state for head
    __shared__ float sh_hd[128];      // fc1 hidden

    // ---- load this thread's W_hh row into registers as packed pairs ----
    u64 w[32];
    {
        const float4* wr = reinterpret_cast<const float4*>(W_hh + j * HID);
        #pragma unroll
        for (int i = 0; i < 16; i++) {
            float4 v = __ldg(wr + i);
            w[2 * i]     = pack2(v.x, v.y);
            w[2 * i + 1] = pack2(v.z, v.w);
        }
    }
    const float wih  = __ldg(W_ih + j);
    const float bias = __ldg(b_ih + j) + __ldg(b_hh + j);

    // ---- init h = 0, c = 0 ----
    if (j < HID) reinterpret_cast<float*>(sh_h)[j] = 0.0f;
    float c_reg = 0.0f;   // valid for j < HID
    __syncthreads();

    // ---- time recurrence ----
    #pragma unroll 1
    for (int t0 = 0; t0 < SEQ; t0 += XCHUNK) {
        // stage XCHUNK x-values for this batch column (strided 8KB in gmem)
        sh_x[j] = __ldg(x + (t0 + j) * BATCH + b);
        __syncthreads();

        #pragma unroll 1
        for (int tt = 0; tt < XCHUNK; tt++) {
            const float xv = sh_x[tt];

            // dot(h, W_hh_row) with packed f32x2 math, 4 acc chains
            u64 a0 = 0ull, a1 = 0ull, a2 = 0ull, a3 = 0ull;
            const ulonglong2* h2 = reinterpret_cast<const ulonglong2*>(sh_h);
            #pragma unroll
            for (int i = 0; i < 16; i += 2) {
                ulonglong2 hv0 = h2[i];
                ulonglong2 hv1 = h2[i + 1];
                a0 = fma2(hv0.x, w[2 * i],     a0);
                a1 = fma2(hv0.y, w[2 * i + 1], a1);
                a2 = fma2(hv1.x, w[2 * i + 2], a2);
                a3 = fma2(hv1.y, w[2 * i + 3], a3);
            }
            float2 s = unpack2(add2(add2(a0, a2), add2(a1, a3)));
            float pre = fmaf(xv, wih, bias) + (s.x + s.y);

            // activation by gate group (g-gate = tanh, rest sigmoid)
            float act = (j >= 128 && j < 192) ? fast_tanh(pre) : fast_sigmoid(pre);
            sh_g[j] = act;
            __syncthreads();

            if (j < HID) {
                float iv = sh_g[j];
                float fv = sh_g[j + 64];
                float gv = sh_g[j + 128];
                float ov = sh_g[j + 192];
                c_reg = fmaf(fv, c_reg, iv * gv);
                reinterpret_cast<float*>(sh_h)[j] = ov * fast_tanh(c_reg);
            }
            __syncthreads();
        }
    }

    // ---- MLP head on cell state: out = (c @ fc1_w.T + fc1_b) @ fc2_w.T + fc2_b ----
    if (j < HID) sh_c[j] = c_reg;
    __syncthreads();

    if (j < 128) {
        const float* fw = fc1_w + j * HID;
        float s = __ldg(fc1_b + j);
        #pragma unroll
        for (int k = 0; k < HID; k++) s = fmaf(__ldg(fw + k), sh_c[k], s);
        sh_hd[j] = s;
    }
    __syncthreads();

    if (j < 5) {
        const float* fw = fc2_w + j * 128;
        float s = __ldg(fc2_b + j);
        #pragma unroll
        for (int k = 0; k < 128; k++) s = fmaf(__ldg(fw + k), sh_hd[k], s);
        out[b * 5 + j] = s;
    }
}

extern "C" void kernel_launch(void* const* d_in, const int* in_sizes, int n_in,
                              void* d_out, int out_size)
{
    const float* x     = (const float*)d_in[0];
    const float* W_ih  = (const float*)d_in[1];
    const float* W_hh  = (const float*)d_in[2];
    const float* b_ih  = (const float*)d_in[3];
    const float* b_hh  = (const float*)d_in[4];
    const float* fc1_w = (const float*)d_in[5];
    const float* fc1_b = (const float*)d_in[6];
    const float* fc2_w = (const float*)d_in[7];
    const float* fc2_b = (const float*)d_in[8];
    float* out = (float*)d_out;

    lstm_fused_kernel<<<BATCH, 256>>>(x, W_ih, W_hh, b_ih, b_hh,
                                      fc1_w, fc1_b, fc2_w, fc2_b, out);
}